// round 14
// baseline (speedup 1.0000x reference)
#include <cuda_runtime.h>
#include <cuda_fp16.h>
#include <cstdint>

#define BATCH 4
#define CH    128
#define CIN   256
#define HH    224
#define WW    224
#define HW    50176
#define NCLS  41

// ---------------------------------------------------------------------------
// scratch (static device globals; no allocs)
// ---------------------------------------------------------------------------
// g_xA: channel-last fp16-pair records: [b][pixel][128 words].
// word cp in [0,64) = add-plane channel pairs, [64,128) = mul-plane pairs.
// One chunk (ci-block of 64 ch) = 32 consecutive words = 128 contiguous bytes.
static __device__ uint32_t g_xA[(size_t)BATCH * HW * 128];
static __device__ float    g_fuse[(size_t)BATCH * CH * HW];    // conv output fp32
static __device__ uint4    g_bt4[36 * 1024];                   // 36 chunks x 16KB SW128 fp16 B images
static __device__ float    g_sum_d[BATCH * NCLS * CH];
static __device__ float    g_sum_f[BATCH * NCLS * CH];
static __device__ float    g_cnt[BATCH * NCLS];
static __device__ float    g_scale[2 * BATCH * CH];

__device__ __forceinline__ float sigmoid_fast(float x) { return 1.f / (1.f + __expf(-x)); }

__device__ __forceinline__ uint32_t smem_u32(const void* p) {
    uint32_t a;
    asm("{ .reg .u64 t; cvta.to.shared.u64 t, %1; cvt.u32.u64 %0, t; }" : "=r"(a) : "l"(p));
    return a;
}

__device__ __forceinline__ void ldsm4(uint32_t* r, uint32_t addr) {
    asm volatile("ldmatrix.sync.aligned.m8n8.x4.shared.b16 {%0,%1,%2,%3}, [%4];"
                 : "=r"(r[0]), "=r"(r[1]), "=r"(r[2]), "=r"(r[3]) : "r"(addr));
}

__device__ __forceinline__ void mma16816(float* c, const uint32_t* a, const uint32_t* b) {
    asm volatile(
        "mma.sync.aligned.m16n8k16.row.col.f32.f16.f16.f32 "
        "{%0,%1,%2,%3}, {%4,%5,%6,%7}, {%8,%9}, {%0,%1,%2,%3};"
        : "+f"(c[0]), "+f"(c[1]), "+f"(c[2]), "+f"(c[3])
        : "r"(a[0]), "r"(a[1]), "r"(a[2]), "r"(a[3]), "r"(b[0]), "r"(b[1]));
}

#define CP_ASYNC16(dst, src) \
    asm volatile("cp.async.cg.shared.global [%0], [%1], 16;" :: "r"(dst), "l"(src) : "memory")
#define CP_ASYNC16_Z(dst, src, sz) \
    asm volatile("cp.async.cg.shared.global [%0], [%1], 16, %2;" :: "r"(dst), "l"(src), "r"(sz) : "memory")
#define CP_COMMIT() asm volatile("cp.async.commit_group;" ::: "memory")
#define CP_WAIT0()  asm volatile("cp.async.wait_group 0;" ::: "memory")

__device__ __forceinline__ uint32_t h2pack(float a, float b) {
    __half2 h = __floats2half2_rn(a, b);
    return *reinterpret_cast<uint32_t*>(&h);
}

// ---------------- zero accumulators ----------------
__global__ void zero_kernel() {
    int i = blockIdx.x * 256 + threadIdx.x;
    if (i < BATCH * NCLS * CH) { g_sum_d[i] = 0.f; g_sum_f[i] = 0.f; }
    if (i < BATCH * NCLS) g_cnt[i] = 0.f;
}

// ---------------- weight prepack: 36 SW128 fp16 images (128 oc x 64 ch) ----------------
__global__ void wprep_kernel(const float* __restrict__ w) {
    int idx = blockIdx.x * 256 + threadIdx.x;
    if (idx >= 36 * CH * 64) return;
    int kk = idx & 63;
    int oc = (idx >> 6) & 127;
    int t  = idx >> 13;          // 0..35 : tap f = t>>2, ci-block = t&3
    int f  = t >> 2;
    int ci = (t & 3) * 64 + kk;
    float wv = w[(size_t)(oc * CIN + ci) * 9 + f];
    uint32_t off = ((uint32_t)oc << 7) + (((uint32_t)kk * 2) ^ (((uint32_t)(oc & 7)) << 4));
    *(__half*)((char*)g_bt4 + (size_t)t * 16384 + off) = __float2half(wv);
}

// ---------------- prep + RA(d) fused ----------------
// grid (HW/256, BATCH); block 256. Each thread: ONE pixel, all 128 channels.
// Writes channel-last g_xA records (two 32B chunks per 16-ch group, sector-complete).
__global__ void prep_ra_kernel(const float* __restrict__ r, const float* __restrict__ dd,
                               const int* __restrict__ label) {
    __shared__ float bins[NCLS * 129];
    __shared__ float cnts[NCLS];

    const int b   = blockIdx.y;
    const int p0  = blockIdx.x * 256;
    const int tid = threadIdx.x;
    const int p   = p0 + tid;

    for (int i = tid; i < NCLS * 129; i += 256) bins[i] = 0.f;
    if (tid < NCLS) cnts[tid] = 0.f;
    __syncthreads();

    const int y = p / WW;
    const int x = p - y * WW;
    const int lab = label[(size_t)b * 896 * 896 + (size_t)(4 * y) * 896 + 4 * x];
    atomicAdd(&cnts[lab], 1.f);

    uint32_t* xb = g_xA + ((size_t)b * HW + p) * 128;
    float* binrow = bins + lab * 129;

    #pragma unroll 1
    for (int cg = 0; cg < 8; cg++) {
        const int c0 = cg * 16;
        float rv[16], dv[16];
        #pragma unroll
        for (int e = 0; e < 16; e++) {
            size_t off = ((size_t)(b * CH + c0 + e)) * HW + p;
            rv[e] = r[off];
            dv[e] = dd[off];
        }
        #pragma unroll
        for (int e = 0; e < 16; e++) atomicAdd(&binrow[c0 + e], dv[e]);

        uint4 a0, a1, m0, m1;
        a0.x = h2pack(rv[0] + dv[0],  rv[1] + dv[1]);
        a0.y = h2pack(rv[2] + dv[2],  rv[3] + dv[3]);
        a0.z = h2pack(rv[4] + dv[4],  rv[5] + dv[5]);
        a0.w = h2pack(rv[6] + dv[6],  rv[7] + dv[7]);
        a1.x = h2pack(rv[8] + dv[8],  rv[9] + dv[9]);
        a1.y = h2pack(rv[10] + dv[10], rv[11] + dv[11]);
        a1.z = h2pack(rv[12] + dv[12], rv[13] + dv[13]);
        a1.w = h2pack(rv[14] + dv[14], rv[15] + dv[15]);
        m0.x = h2pack(rv[0] * sigmoid_fast(dv[0]),  rv[1] * sigmoid_fast(dv[1]));
        m0.y = h2pack(rv[2] * sigmoid_fast(dv[2]),  rv[3] * sigmoid_fast(dv[3]));
        m0.z = h2pack(rv[4] * sigmoid_fast(dv[4]),  rv[5] * sigmoid_fast(dv[5]));
        m0.w = h2pack(rv[6] * sigmoid_fast(dv[6]),  rv[7] * sigmoid_fast(dv[7]));
        m1.x = h2pack(rv[8] * sigmoid_fast(dv[8]),  rv[9] * sigmoid_fast(dv[9]));
        m1.y = h2pack(rv[10] * sigmoid_fast(dv[10]), rv[11] * sigmoid_fast(dv[11]));
        m1.z = h2pack(rv[12] * sigmoid_fast(dv[12]), rv[13] * sigmoid_fast(dv[13]));
        m1.w = h2pack(rv[14] * sigmoid_fast(dv[14]), rv[15] * sigmoid_fast(dv[15]));

        *reinterpret_cast<uint4*>(xb + cg * 8)          = a0;
        *reinterpret_cast<uint4*>(xb + cg * 8 + 4)      = a1;
        *reinterpret_cast<uint4*>(xb + 64 + cg * 8)     = m0;
        *reinterpret_cast<uint4*>(xb + 64 + cg * 8 + 4) = m1;
    }
    __syncthreads();

    for (int i = tid; i < NCLS * CH; i += 256) {
        int k = i >> 7;
        int c = i & 127;
        atomicAdd(&g_sum_d[((size_t)b * NCLS + k) * CH + c], bins[k * 129 + c]);
    }
    if (tid < NCLS) atomicAdd(&g_cnt[b * NCLS + tid], cnts[tid]);
}

// ---------------- RA finalize ----------------
__global__ void ra_finalize_kernel(const float* __restrict__ w1_d, const float* __restrict__ w2_d,
                                   const float* __restrict__ w1_f, const float* __restrict__ w2_f) {
    const int which = blockIdx.x & 1;
    const int b     = blockIdx.x >> 1;
    const float* sums = which ? g_sum_f : g_sum_d;
    const float* w1   = which ? w1_f : w1_d;
    const float* w2   = which ? w2_f : w2_d;

    __shared__ float att[CH];
    __shared__ float hid[8];
    const int c = threadIdx.x;  // 128 threads

    float s1 = 0.f, s2 = 0.f;
    for (int k = 0; k < NCLS; k++) {
        float cnt = g_cnt[b * NCLS + k];
        float m = sums[((size_t)b * NCLS + k) * CH + c] / fmaxf(cnt, 1.f);
        s1 += m;
        s2 += m * m;
    }
    float nrm = fmaxf(sqrtf(s2), 1e-12f);
    att[c] = s1 / nrm;
    __syncthreads();

    if (c < 8) {
        float h = 0.f;
        for (int j = 0; j < CH; j++) h += att[j] * w1[c * CH + j];
        hid[c] = fmaxf(h, 0.f);
    }
    __syncthreads();

    float o = 0.f;
    #pragma unroll
    for (int j = 0; j < 8; j++) o += hid[j] * w2[c * 8 + j];
    g_scale[(which * BATCH + b) * CH + c] = 1.f / (1.f + expf(-o));
}

// ---------------- conv: fp16 mma.sync, all-cp.async 2-stage pipeline, fused RA(fuse) ----------------
// CTA: 128 pixels x 128 oc.  36 chunks = 9 taps x 4 ci-blocks of 64 channels.
// Stage (32KB): A tile 16KB (128 px rows x 64 fp16 ch, SW128) + B tile 16KB.
// A row = 128 contiguous bytes of g_xA -> 4 cp.async.16 per thread (zfill for halo).
#define CONV_SMEM 65536

__global__ __launch_bounds__(256, 2) void conv_mma_kernel(const int* __restrict__ label) {
    extern __shared__ __align__(1024) char smem[];
    const uint32_t sb = smem_u32(smem);
    const int tid  = threadIdx.x;
    const int wid  = tid >> 5;
    const int lane = tid & 31;
    const int b    = blockIdx.y;
    const int p0   = blockIdx.x * 128;

    const int wm = wid & 1;        // M warp (0..1) -> 64 pixels
    const int wn = wid >> 1;       // N warp (0..3) -> 32 oc
    const int rln  = lane & 7;
    const int quad = lane >> 3;

    const int a_row_off = rln + ((quad & 1) << 3);
    const uint32_t a_kb = (uint32_t)(quad >> 1) << 4;
    const int b_oc_off  = rln + ((quad >> 1) << 3);
    const uint32_t b_kb = (uint32_t)(quad & 1) << 4;
    const uint32_t lxor = (uint32_t)rln << 4;

    const uint32_t aBase = sb + (uint32_t)(wm * 64 + a_row_off) * 128;
    const uint32_t bBase = sb + 16384 + (uint32_t)(wn * 32 + b_oc_off) * 128;

    // loader mapping: 2 threads per pixel row (half = 32 ch = 64 B each)
    const int row  = tid >> 1;
    const int half = tid & 1;
    const int p    = p0 + row;
    const int py   = p / WW;
    const int px   = p - py * WW;
    const uint32_t swx = (uint32_t)(row & 7) << 4;
    const char* xrec = (const char*)(g_xA + (size_t)b * HW * 128);

    float acc[4][4][4];
    #pragma unroll
    for (int i = 0; i < 4; i++)
        #pragma unroll
        for (int j = 0; j < 4; j++)
            #pragma unroll
            for (int k = 0; k < 4; k++) acc[i][j][k] = 0.f;

    // ---- prologue: chunk 0 -> stage 0 ----
    {
        const int iy = py - 1, ix = px - 1;
        const bool valid = ((unsigned)iy < (unsigned)HH) && ((unsigned)ix < (unsigned)WW);
        const int q = valid ? (iy * WW + ix) : 0;
        const uint32_t sz = valid ? 16u : 0u;
        const char* asrc = xrec + (size_t)q * 512 + half * 64;
        const uint32_t ad = sb + (uint32_t)row * 128;
        #pragma unroll
        for (int i = 0; i < 4; i++)
            CP_ASYNC16_Z(ad + (((uint32_t)(half * 64 + 16 * i)) ^ swx), asrc + 16 * i, sz);
        const char* bsrc = (const char*)g_bt4 + tid * 16;
        uint32_t bd = sb + 16384 + tid * 16;
        #pragma unroll
        for (int i = 0; i < 4; i++) CP_ASYNC16(bd + i * 4096, bsrc + i * 4096);
        CP_COMMIT();
    }
    CP_WAIT0();
    __syncthreads();

    for (int c = 0; c < 36; c++) {
        const int s = c & 1;

        // prefetch chunk c+1 into stage s^1 (pure cp.async; overlaps MMA below)
        if (c < 35) {
            const int cn = c + 1;
            const int f  = cn >> 2;
            const int cc = cn & 3;
            const int fy = f / 3;
            const int iy = py + fy - 1;
            const int ix = px + (f - fy * 3) - 1;
            const bool valid = ((unsigned)iy < (unsigned)HH) && ((unsigned)ix < (unsigned)WW);
            const int q = valid ? (iy * WW + ix) : 0;
            const uint32_t sz = valid ? 16u : 0u;
            const char* asrc = xrec + (size_t)q * 512 + cc * 128 + half * 64;
            const uint32_t ad = sb + (uint32_t)(s ^ 1) * 32768 + (uint32_t)row * 128;
            #pragma unroll
            for (int i = 0; i < 4; i++)
                CP_ASYNC16_Z(ad + (((uint32_t)(half * 64 + 16 * i)) ^ swx), asrc + 16 * i, sz);
            const char* bsrc = (const char*)g_bt4 + (size_t)cn * 16384 + tid * 16;
            uint32_t bd = sb + (uint32_t)(s ^ 1) * 32768 + 16384 + tid * 16;
            #pragma unroll
            for (int i = 0; i < 4; i++) CP_ASYNC16(bd + i * 4096, bsrc + i * 4096);
            CP_COMMIT();
        }

        // ---- MMA on stage s: K = 64 ch = 4 k16 steps ----
        const uint32_t aB = aBase + (uint32_t)s * 32768;
        const uint32_t bB = bBase + (uint32_t)s * 32768;
        #pragma unroll
        for (int ks = 0; ks < 4; ks++) {
            const uint32_t aco = ((uint32_t)(ks * 32) + a_kb) ^ lxor;
            const uint32_t bco = ((uint32_t)(ks * 32) + b_kb) ^ lxor;

            uint32_t Bf[2][4];
            ldsm4(Bf[0], bB + bco);
            ldsm4(Bf[1], bB + 2048 + bco);
            #pragma unroll
            for (int mf = 0; mf < 4; mf++) {
                uint32_t Af[4];
                ldsm4(Af, aB + mf * 2048 + aco);
                mma16816(acc[mf][0], Af, Bf[0]);
                mma16816(acc[mf][1], Af, Bf[0] + 2);
                mma16816(acc[mf][2], Af, Bf[1]);
                mma16816(acc[mf][3], Af, Bf[1] + 2);
            }
        }

        if (c < 35) CP_WAIT0();
        __syncthreads();
    }

    // ---- fused epilogue: write g_fuse + RA(fuse) bins ----
    float* bins = (float*)smem;                    // 41*129 floats = 21156 B
    int*   slb  = (int*)(smem + 21248);            // 128 labels
    for (int i = tid; i < NCLS * 129; i += 256) bins[i] = 0.f;
    if (tid < 128) {
        int pp = p0 + tid;
        int yy = pp / WW;
        int xx = pp - yy * WW;
        slb[tid] = label[(size_t)b * 896 * 896 + (size_t)(4 * yy) * 896 + 4 * xx];
    }
    __syncthreads();

    float* fb = g_fuse + (size_t)b * CH * HW;
    const int prl = wm * 64 + (lane >> 2);
    const int oc0 = wn * 32 + (lane & 3) * 2;
    #pragma unroll
    for (int mf = 0; mf < 4; mf++) {
        const int px0 = prl + mf * 16;
        const int la  = slb[px0];
        const int lb2 = slb[px0 + 8];
        #pragma unroll
        for (int nf = 0; nf < 4; nf++) {
            const int oc = oc0 + nf * 8;
            float v0 = acc[mf][nf][0], v1 = acc[mf][nf][1];
            float v2 = acc[mf][nf][2], v3 = acc[mf][nf][3];
            fb[(size_t)oc * HW + p0 + px0]           = v0;
            fb[(size_t)(oc + 1) * HW + p0 + px0]     = v1;
            fb[(size_t)oc * HW + p0 + px0 + 8]       = v2;
            fb[(size_t)(oc + 1) * HW + p0 + px0 + 8] = v3;
            atomicAdd(&bins[la * 129 + oc], v0);
            atomicAdd(&bins[la * 129 + oc + 1], v1);
            atomicAdd(&bins[lb2 * 129 + oc], v2);
            atomicAdd(&bins[lb2 * 129 + oc + 1], v3);
        }
    }
    __syncthreads();
    for (int i = tid; i < NCLS * CH; i += 256) {
        int k = i >> 7;
        int c = i & 127;
        atomicAdd(&g_sum_f[((size_t)b * NCLS + k) * CH + c], bins[k * 129 + c]);
    }
}

// ---------------- final: out = fuse*scale_f + d*scale_d ----------------
__global__ void final_kernel(const float* __restrict__ dd, float* __restrict__ out) {
    int idx = blockIdx.x * 256 + threadIdx.x;
    const int n4 = BATCH * CH * HW / 4;
    if (idx >= n4) return;
    int i = idx * 4;
    int bc = i / HW;
    int b = bc >> 7;
    int c = bc & (CH - 1);
    float sd = g_scale[b * CH + c];
    float sf = g_scale[(BATCH + b) * CH + c];
    float4 dv = *reinterpret_cast<const float4*>(dd + i);
    float4 fv = *reinterpret_cast<const float4*>(g_fuse + i);
    float4 o;
    o.x = fv.x * sf + dv.x * sd;
    o.y = fv.y * sf + dv.y * sd;
    o.z = fv.z * sf + dv.z * sd;
    o.w = fv.w * sf + dv.w * sd;
    *reinterpret_cast<float4*>(out + i) = o;
}

// ---------------- launcher ----------------
extern "C" void kernel_launch(void* const* d_in, const int* in_sizes, int n_in,
                              void* d_out, int out_size) {
    const float* r      = (const float*)d_in[0];
    const float* d      = (const float*)d_in[1];
    const int*   label  = (const int*)  d_in[2];
    const float* w_fuse = (const float*)d_in[3];
    const float* w1_d   = (const float*)d_in[4];
    const float* w2_d   = (const float*)d_in[5];
    const float* w1_f   = (const float*)d_in[6];
    const float* w2_f   = (const float*)d_in[7];
    float* out = (float*)d_out;

    static int smem_set = 0;
    if (!smem_set) {
        cudaFuncSetAttribute(conv_mma_kernel, cudaFuncAttributeMaxDynamicSharedMemorySize, CONV_SMEM);
        smem_set = 1;
    }

    const int n4 = BATCH * CH * HW / 4;

    zero_kernel<<<(BATCH * NCLS * CH + 255) / 256, 256>>>();                       // 1
    wprep_kernel<<<(36 * CH * 64 + 255) / 256, 256>>>(w_fuse);                     // 2
    prep_ra_kernel<<<dim3(HW / 256, BATCH), 256>>>(r, d, label);                   // 3
    conv_mma_kernel<<<dim3(HW / 128, BATCH), 256, CONV_SMEM>>>(label);             // 4
    ra_finalize_kernel<<<2 * BATCH, CH>>>(w1_d, w2_d, w1_f, w2_f);                 // 5
    final_kernel<<<(n4 + 255) / 256, 256>>>(d, out);                               // 6
}

// round 15
// speedup vs baseline: 1.6231x; 1.6231x over previous
#include <cuda_runtime.h>
#include <cuda_fp16.h>
#include <cstdint>

#define BATCH 4
#define CH    128
#define CIN   256
#define HH    224
#define WW    224
#define HW    50176
#define NCLS  41

// ---------------------------------------------------------------------------
// scratch (static device globals; no allocs)
// ---------------------------------------------------------------------------
// g_xh2: fp16 channel-PAIR packed planes: word = (fp16 x[2cp], fp16 x[2cp+1]) per pixel.
// cp in [0,64) = add-plane pairs, [64,128) = mul-plane pairs.
static __device__ uint32_t g_xh2[(size_t)BATCH * 128 * HW];
static __device__ __half   g_fuse_h[(size_t)BATCH * CH * HW];  // conv output (fp16, channel-major)
static __device__ uint4    g_bt4[36 * 1024];                   // 36 chunks x 16KB SW128 fp16 B images
static __device__ float    g_sum_d[BATCH * NCLS * CH];
static __device__ float    g_sum_f[BATCH * NCLS * CH];
static __device__ float    g_cnt[BATCH * NCLS];
static __device__ float    g_scale[2 * BATCH * CH];

__device__ __forceinline__ float sigmoid_fast(float x) { return 1.f / (1.f + __expf(-x)); }

__device__ __forceinline__ uint32_t smem_u32(const void* p) {
    uint32_t a;
    asm("{ .reg .u64 t; cvta.to.shared.u64 t, %1; cvt.u32.u64 %0, t; }" : "=r"(a) : "l"(p));
    return a;
}

__device__ __forceinline__ void ldsm4(uint32_t* r, uint32_t addr) {
    asm volatile("ldmatrix.sync.aligned.m8n8.x4.shared.b16 {%0,%1,%2,%3}, [%4];"
                 : "=r"(r[0]), "=r"(r[1]), "=r"(r[2]), "=r"(r[3]) : "r"(addr));
}

__device__ __forceinline__ void mma16816(float* c, const uint32_t* a, const uint32_t* b) {
    asm volatile(
        "mma.sync.aligned.m16n8k16.row.col.f32.f16.f16.f32 "
        "{%0,%1,%2,%3}, {%4,%5,%6,%7}, {%8,%9}, {%0,%1,%2,%3};"
        : "+f"(c[0]), "+f"(c[1]), "+f"(c[2]), "+f"(c[3])
        : "r"(a[0]), "r"(a[1]), "r"(a[2]), "r"(a[3]), "r"(b[0]), "r"(b[1]));
}

#define CP_ASYNC16(dst, src) \
    asm volatile("cp.async.cg.shared.global [%0], [%1], 16;" :: "r"(dst), "l"(src) : "memory")
#define CP_COMMIT() asm volatile("cp.async.commit_group;" ::: "memory")
#define CP_WAIT0()  asm volatile("cp.async.wait_group 0;" ::: "memory")

__device__ __forceinline__ uint32_t h2pack(float a, float b) {
    __half2 h = __floats2half2_rn(a, b);
    return *reinterpret_cast<uint32_t*>(&h);
}

// ---------------- zero accumulators ----------------
__global__ void zero_kernel() {
    int i = blockIdx.x * 256 + threadIdx.x;
    if (i < BATCH * NCLS * CH) { g_sum_d[i] = 0.f; g_sum_f[i] = 0.f; }
    if (i < BATCH * NCLS) g_cnt[i] = 0.f;
}

// ---------------- weight prepack: 36 SW128 fp16 images (128 oc x 64 ch) ----------------
__global__ void wprep_kernel(const float* __restrict__ w) {
    int idx = blockIdx.x * 256 + threadIdx.x;
    if (idx >= 36 * CH * 64) return;
    int kk = idx & 63;
    int oc = (idx >> 6) & 127;
    int t  = idx >> 13;          // 0..35 : tap f = t>>2, ci-block = t&3
    int f  = t >> 2;
    int ci = (t & 3) * 64 + kk;
    float wv = w[(size_t)(oc * CIN + ci) * 9 + f];
    uint32_t off = ((uint32_t)oc << 7) + (((uint32_t)kk * 2) ^ (((uint32_t)(oc & 7)) << 4));
    *(__half*)((char*)g_bt4 + (size_t)t * 16384 + off) = __float2half(wv);
}

// ---------------- prep + RA(d) fused ----------------
// grid (HW/1024, BATCH, 4); block 256. Each block: 1024 pixels x 32 channels.
__global__ void prep_ra_kernel(const float* __restrict__ r, const float* __restrict__ dd,
                               const int* __restrict__ label) {
    __shared__ float bins[NCLS * 33];
    __shared__ float cnts[NCLS];
    __shared__ int   slab[1024];

    const int b   = blockIdx.y;
    const int c0  = blockIdx.z * 32;
    const int p0  = blockIdx.x * 1024;
    const int tid = threadIdx.x;

    for (int i = tid; i < NCLS * 33; i += 256) bins[i] = 0.f;
    if (tid < NCLS) cnts[tid] = 0.f;
    for (int i = tid; i < 1024; i += 256) {
        int p = p0 + i;
        int y = p / WW;
        int x = p - y * WW;
        slab[i] = label[(size_t)b * 896 * 896 + (size_t)(4 * y) * 896 + 4 * x];
    }
    __syncthreads();

    if (blockIdx.z == 0) {
        for (int i = tid; i < 1024; i += 256) atomicAdd(&cnts[slab[i]], 1.f);
    }

    const int i4 = tid * 4;
    const int l0 = slab[i4], l1 = slab[i4 + 1], l2 = slab[i4 + 2], l3 = slab[i4 + 3];
    uint32_t* xb = g_xh2 + (size_t)b * 128 * HW;

    for (int c = 0; c < 32; c += 2) {
        size_t off0 = ((size_t)(b * CH + c0 + c)) * HW + p0 + i4;
        float4 rv0 = *reinterpret_cast<const float4*>(r + off0);
        float4 dv0 = *reinterpret_cast<const float4*>(dd + off0);
        float4 rv1 = *reinterpret_cast<const float4*>(r + off0 + HW);
        float4 dv1 = *reinterpret_cast<const float4*>(dd + off0 + HW);

        atomicAdd(&bins[l0 * 33 + c], dv0.x);
        atomicAdd(&bins[l1 * 33 + c], dv0.y);
        atomicAdd(&bins[l2 * 33 + c], dv0.z);
        atomicAdd(&bins[l3 * 33 + c], dv0.w);
        atomicAdd(&bins[l0 * 33 + c + 1], dv1.x);
        atomicAdd(&bins[l1 * 33 + c + 1], dv1.y);
        atomicAdd(&bins[l2 * 33 + c + 1], dv1.z);
        atomicAdd(&bins[l3 * 33 + c + 1], dv1.w);

        uint4 ap, mp;
        ap.x = h2pack(rv0.x + dv0.x, rv1.x + dv1.x);
        ap.y = h2pack(rv0.y + dv0.y, rv1.y + dv1.y);
        ap.z = h2pack(rv0.z + dv0.z, rv1.z + dv1.z);
        ap.w = h2pack(rv0.w + dv0.w, rv1.w + dv1.w);
        mp.x = h2pack(rv0.x * sigmoid_fast(dv0.x), rv1.x * sigmoid_fast(dv1.x));
        mp.y = h2pack(rv0.y * sigmoid_fast(dv0.y), rv1.y * sigmoid_fast(dv1.y));
        mp.z = h2pack(rv0.z * sigmoid_fast(dv0.z), rv1.z * sigmoid_fast(dv1.z));
        mp.w = h2pack(rv0.w * sigmoid_fast(dv0.w), rv1.w * sigmoid_fast(dv1.w));

        const int cp = (c0 + c) >> 1;      // pair index within add plane
        *reinterpret_cast<uint4*>(xb + ((size_t)cp) * HW + p0 + i4)        = ap;
        *reinterpret_cast<uint4*>(xb + ((size_t)(64 + cp)) * HW + p0 + i4) = mp;
    }
    __syncthreads();

    for (int i = tid; i < NCLS * 32; i += 256) {
        int k = i >> 5;
        int c = i & 31;
        atomicAdd(&g_sum_d[((size_t)b * NCLS + k) * CH + c0 + c], bins[k * 33 + c]);
    }
    if (blockIdx.z == 0 && tid < NCLS) atomicAdd(&g_cnt[b * NCLS + tid], cnts[tid]);
}

// ---------------- RA finalize ----------------
__global__ void ra_finalize_kernel(const float* __restrict__ w1_d, const float* __restrict__ w2_d,
                                   const float* __restrict__ w1_f, const float* __restrict__ w2_f) {
    const int which = blockIdx.x & 1;
    const int b     = blockIdx.x >> 1;
    const float* sums = which ? g_sum_f : g_sum_d;
    const float* w1   = which ? w1_f : w1_d;
    const float* w2   = which ? w2_f : w2_d;

    __shared__ float att[CH];
    __shared__ float hid[8];
    const int c = threadIdx.x;  // 128 threads

    float s1 = 0.f, s2 = 0.f;
    for (int k = 0; k < NCLS; k++) {
        float cnt = g_cnt[b * NCLS + k];
        float m = sums[((size_t)b * NCLS + k) * CH + c] / fmaxf(cnt, 1.f);
        s1 += m;
        s2 += m * m;
    }
    float nrm = fmaxf(sqrtf(s2), 1e-12f);
    att[c] = s1 / nrm;
    __syncthreads();

    if (c < 8) {
        float h = 0.f;
        for (int j = 0; j < CH; j++) h += att[j] * w1[c * CH + j];
        hid[c] = fmaxf(h, 0.f);
    }
    __syncthreads();

    float o = 0.f;
    #pragma unroll
    for (int j = 0; j < 8; j++) o += hid[j] * w2[c * 8 + j];
    g_scale[(which * BATCH + b) * CH + c] = 1.f / (1.f + expf(-o));
}

// ---------------- conv: mma.sync fp16 single-term, 2-stage pipeline, fused RA(fuse) ----------------
// CTA: 128 pixels x 128 oc.  36 chunks = 9 taps x 4 ci-blocks of 64 channels.
// Stage (32KB): A tile 16KB (128 px rows x 64 fp16 ch, SW128) + B tile 16KB (128 oc x 64 ch).
// 2 stages = 64KB.  Prefetch chunk c+1 (A LDGs in regs, B cp.async) overlaps MMA of chunk c;
// prefetched-A STS issued mid-MMA-loop (after ks=2) to shorten the per-chunk serial tail.
#define CONV_SMEM 65536

__device__ __forceinline__ void conv_store_a(char* aRow, const uint32_t* xs,
                                             int half, uint32_t swx) {
    #pragma unroll
    for (int q = 0; q < 4; q++) {
        uint4 v;
        v.x = xs[4 * q];  v.y = xs[4 * q + 1];  v.z = xs[4 * q + 2];  v.w = xs[4 * q + 3];
        uint32_t co = ((uint32_t)(half * 64 + 16 * q)) ^ swx;
        *(uint4*)(aRow + co) = v;
    }
}

__global__ __launch_bounds__(256, 2) void conv_mma_kernel(const int* __restrict__ label) {
    extern __shared__ __align__(1024) char smem[];
    const uint32_t sb = smem_u32(smem);
    const int tid  = threadIdx.x;
    const int wid  = tid >> 5;
    const int lane = tid & 31;
    const int b    = blockIdx.y;
    const int p0   = blockIdx.x * 128;

    const int wm = wid & 1;        // M warp (0..1) -> 64 pixels
    const int wn = wid >> 1;       // N warp (0..3) -> 32 oc
    const int rln  = lane & 7;
    const int quad = lane >> 3;

    const int a_row_off = rln + ((quad & 1) << 3);
    const uint32_t a_kb = (uint32_t)(quad >> 1) << 4;
    const int b_oc_off  = rln + ((quad >> 1) << 3);
    const uint32_t b_kb = (uint32_t)(quad & 1) << 4;
    const uint32_t lxor = (uint32_t)rln << 4;

    const uint32_t aBase = sb + (uint32_t)(wm * 64 + a_row_off) * 128;
    const uint32_t bBase = sb + 16384 + (uint32_t)(wn * 32 + b_oc_off) * 128;

    // loader mapping: 2 threads per pixel row, each 16 channel-pairs (32 ch)
    const int row  = tid >> 1;
    const int half = tid & 1;
    const int p    = p0 + row;
    const int py   = p / WW;
    const int px   = p - py * WW;
    const uint32_t swx = (uint32_t)(row & 7) << 4;

    float acc[4][4][4];
    #pragma unroll
    for (int i = 0; i < 4; i++)
        #pragma unroll
        for (int j = 0; j < 4; j++)
            #pragma unroll
            for (int k = 0; k < 4; k++) acc[i][j][k] = 0.f;

    uint32_t xs[16];

    // ---- prologue: chunk 0 -> stage 0 ----
    {
        const int iy = py - 1, ix = px - 1;
        const bool valid = ((unsigned)iy < (unsigned)HH) && ((unsigned)ix < (unsigned)WW);
        const uint32_t* sp = g_xh2 + ((size_t)(b * 128 + half * 16)) * HW + (iy * WW + ix);
        #pragma unroll
        for (int e = 0; e < 16; e++) xs[e] = valid ? sp[(size_t)e * HW] : 0u;
        const char* bsrc = (const char*)g_bt4 + tid * 16;
        uint32_t bd = sb + 16384 + tid * 16;
        #pragma unroll
        for (int i = 0; i < 4; i++) CP_ASYNC16(bd + i * 4096, bsrc + i * 4096);
        CP_COMMIT();
        conv_store_a(smem + row * 128, xs, half, swx);
    }
    CP_WAIT0();
    __syncthreads();

    for (int c = 0; c < 36; c++) {
        const int s = c & 1;

        // prefetch chunk c+1: A LDGs into regs (latency hides under MMA), B via cp.async
        if (c < 35) {
            const int cn = c + 1;
            const int f  = cn >> 2;
            const int cc = cn & 3;
            const int fy = f / 3;
            const int iy = py + fy - 1;
            const int ix = px + (f - fy * 3) - 1;
            const bool valid = ((unsigned)iy < (unsigned)HH) && ((unsigned)ix < (unsigned)WW);
            const uint32_t* sp = g_xh2 + ((size_t)(b * 128 + cc * 32 + half * 16)) * HW
                                       + (iy * WW + ix);
            #pragma unroll
            for (int e = 0; e < 16; e++) xs[e] = valid ? sp[(size_t)e * HW] : 0u;

            const char* bsrc = (const char*)g_bt4 + (size_t)cn * 16384 + tid * 16;
            uint32_t bd = sb + (uint32_t)(s ^ 1) * 32768 + 16384 + tid * 16;
            #pragma unroll
            for (int i = 0; i < 4; i++) CP_ASYNC16(bd + i * 4096, bsrc + i * 4096);
            CP_COMMIT();
        }

        // ---- MMA on stage s: K = 64 ch = 4 k16 steps, single fp16 term ----
        const uint32_t aB = aBase + (uint32_t)s * 32768;
        const uint32_t bB = bBase + (uint32_t)s * 32768;
        #pragma unroll
        for (int ks = 0; ks < 4; ks++) {
            const uint32_t aco = ((uint32_t)(ks * 32) + a_kb) ^ lxor;
            const uint32_t bco = ((uint32_t)(ks * 32) + b_kb) ^ lxor;

            uint32_t Bf[2][4];
            ldsm4(Bf[0], bB + bco);
            ldsm4(Bf[1], bB + 2048 + bco);
            #pragma unroll
            for (int mf = 0; mf < 4; mf++) {
                uint32_t Af[4];
                ldsm4(Af, aB + mf * 2048 + aco);
                mma16816(acc[mf][0], Af, Bf[0]);
                mma16816(acc[mf][1], Af, Bf[0] + 2);
                mma16816(acc[mf][2], Af, Bf[1]);
                mma16816(acc[mf][3], Af, Bf[1] + 2);
            }
            // mid-loop: drop prefetched A into the other stage, freeing xs early
            if (ks == 2 && c < 35) {
                conv_store_a(smem + (size_t)(s ^ 1) * 32768 + row * 128, xs, half, swx);
            }
        }

        CP_WAIT0();
        __syncthreads();
    }

    // ---- fused epilogue: write g_fuse_h (fp16) + RA(fuse) bins ----
    float* bins = (float*)smem;                    // 41*129 floats = 21156 B
    int*   slb  = (int*)(smem + 21248);            // 128 labels
    for (int i = tid; i < NCLS * 129; i += 256) bins[i] = 0.f;
    if (tid < 128) {
        int pp = p0 + tid;
        int yy = pp / WW;
        int xx = pp - yy * WW;
        slb[tid] = label[(size_t)b * 896 * 896 + (size_t)(4 * yy) * 896 + 4 * xx];
    }
    __syncthreads();

    __half* fb = g_fuse_h + (size_t)b * CH * HW;
    const int prl = wm * 64 + (lane >> 2);
    const int oc0 = wn * 32 + (lane & 3) * 2;
    #pragma unroll
    for (int mf = 0; mf < 4; mf++) {
        const int px0 = prl + mf * 16;
        const int la  = slb[px0];
        const int lb2 = slb[px0 + 8];
        #pragma unroll
        for (int nf = 0; nf < 4; nf++) {
            const int oc = oc0 + nf * 8;
            float v0 = acc[mf][nf][0], v1 = acc[mf][nf][1];
            float v2 = acc[mf][nf][2], v3 = acc[mf][nf][3];
            fb[(size_t)oc * HW + p0 + px0]           = __float2half(v0);
            fb[(size_t)(oc + 1) * HW + p0 + px0]     = __float2half(v1);
            fb[(size_t)oc * HW + p0 + px0 + 8]       = __float2half(v2);
            fb[(size_t)(oc + 1) * HW + p0 + px0 + 8] = __float2half(v3);
            atomicAdd(&bins[la * 129 + oc], v0);
            atomicAdd(&bins[la * 129 + oc + 1], v1);
            atomicAdd(&bins[lb2 * 129 + oc], v2);
            atomicAdd(&bins[lb2 * 129 + oc + 1], v3);
        }
    }
    __syncthreads();
    for (int i = tid; i < NCLS * CH; i += 256) {
        int k = i >> 7;
        int c = i & 127;
        atomicAdd(&g_sum_f[((size_t)b * NCLS + k) * CH + c], bins[k * 129 + c]);
    }
}

// ---------------- final: out = fuse*scale_f + d*scale_d (fuse fp16, 8 px/thread) ----------------
__global__ void final_kernel(const float* __restrict__ dd, float* __restrict__ out) {
    int idx = blockIdx.x * 256 + threadIdx.x;
    const int n8 = BATCH * CH * HW / 8;
    if (idx >= n8) return;
    int i = idx * 8;
    int bc = i / HW;
    int b = bc >> 7;
    int c = bc & (CH - 1);
    float sd = g_scale[b * CH + c];
    float sf = g_scale[(BATCH + b) * CH + c];

    uint4 fv = *reinterpret_cast<const uint4*>(g_fuse_h + i);   // 8 halfs
    float4 d0 = *reinterpret_cast<const float4*>(dd + i);
    float4 d1 = *reinterpret_cast<const float4*>(dd + i + 4);

    float2 f0 = __half22float2(*reinterpret_cast<__half2*>(&fv.x));
    float2 f1 = __half22float2(*reinterpret_cast<__half2*>(&fv.y));
    float2 f2 = __half22float2(*reinterpret_cast<__half2*>(&fv.z));
    float2 f3 = __half22float2(*reinterpret_cast<__half2*>(&fv.w));

    float4 o0, o1;
    o0.x = f0.x * sf + d0.x * sd;
    o0.y = f0.y * sf + d0.y * sd;
    o0.z = f1.x * sf + d0.z * sd;
    o0.w = f1.y * sf + d0.w * sd;
    o1.x = f2.x * sf + d1.x * sd;
    o1.y = f2.y * sf + d1.y * sd;
    o1.z = f3.x * sf + d1.z * sd;
    o1.w = f3.y * sf + d1.w * sd;
    *reinterpret_cast<float4*>(out + i)     = o0;
    *reinterpret_cast<float4*>(out + i + 4) = o1;
}

// ---------------- launcher ----------------
extern "C" void kernel_launch(void* const* d_in, const int* in_sizes, int n_in,
                              void* d_out, int out_size) {
    const float* r      = (const float*)d_in[0];
    const float* d      = (const float*)d_in[1];
    const int*   label  = (const int*)  d_in[2];
    const float* w_fuse = (const float*)d_in[3];
    const float* w1_d   = (const float*)d_in[4];
    const float* w2_d   = (const float*)d_in[5];
    const float* w1_f   = (const float*)d_in[6];
    const float* w2_f   = (const float*)d_in[7];
    float* out = (float*)d_out;

    static int smem_set = 0;
    if (!smem_set) {
        cudaFuncSetAttribute(conv_mma_kernel, cudaFuncAttributeMaxDynamicSharedMemorySize, CONV_SMEM);
        smem_set = 1;
    }

    const int n8 = BATCH * CH * HW / 8;

    zero_kernel<<<(BATCH * NCLS * CH + 255) / 256, 256>>>();                       // 1
    wprep_kernel<<<(36 * CH * 64 + 255) / 256, 256>>>(w_fuse);                     // 2
    prep_ra_kernel<<<dim3(HW / 1024, BATCH, 4), 256>>>(r, d, label);               // 3
    conv_mma_kernel<<<dim3(HW / 128, BATCH), 256, CONV_SMEM>>>(label);             // 4
    ra_finalize_kernel<<<2 * BATCH, CH>>>(w1_d, w2_d, w1_f, w2_f);                 // 5
    final_kernel<<<(n8 + 255) / 256, 256>>>(d, out);                               // 6
}

// round 16
// speedup vs baseline: 1.6638x; 1.0251x over previous
#include <cuda_runtime.h>
#include <cuda_fp16.h>
#include <cstdint>

#define BATCH 4
#define CH    128
#define CIN   256
#define HH    224
#define WW    224
#define HW    50176
#define NCLS  41

// ---------------------------------------------------------------------------
// scratch (static device globals; no allocs)
// ---------------------------------------------------------------------------
// g_xh2: fp16 channel-PAIR packed planes: word = (fp16 x[2cp], fp16 x[2cp+1]) per pixel.
// cp in [0,64) = add-plane pairs, [64,128) = mul-plane pairs.
static __device__ uint32_t g_xh2[(size_t)BATCH * 128 * HW];
static __device__ __half   g_fuse_h[(size_t)BATCH * CH * HW];  // conv output (fp16, channel-major)
static __device__ uint4    g_bt4[36 * 1024];                   // 36 chunks x 16KB SW128 fp16 B images
static __device__ float    g_sum_d[BATCH * NCLS * CH];
static __device__ float    g_sum_f[BATCH * NCLS * CH];
static __device__ float    g_cnt[BATCH * NCLS];
static __device__ float    g_scale[2 * BATCH * CH];

__device__ __forceinline__ float sigmoid_fast(float x) { return 1.f / (1.f + __expf(-x)); }

__device__ __forceinline__ uint32_t smem_u32(const void* p) {
    uint32_t a;
    asm("{ .reg .u64 t; cvta.to.shared.u64 t, %1; cvt.u32.u64 %0, t; }" : "=r"(a) : "l"(p));
    return a;
}

__device__ __forceinline__ void ldsm4(uint32_t* r, uint32_t addr) {
    asm volatile("ldmatrix.sync.aligned.m8n8.x4.shared.b16 {%0,%1,%2,%3}, [%4];"
                 : "=r"(r[0]), "=r"(r[1]), "=r"(r[2]), "=r"(r[3]) : "r"(addr));
}

__device__ __forceinline__ void mma16816(float* c, const uint32_t* a, const uint32_t* b) {
    asm volatile(
        "mma.sync.aligned.m16n8k16.row.col.f32.f16.f16.f32 "
        "{%0,%1,%2,%3}, {%4,%5,%6,%7}, {%8,%9}, {%0,%1,%2,%3};"
        : "+f"(c[0]), "+f"(c[1]), "+f"(c[2]), "+f"(c[3])
        : "r"(a[0]), "r"(a[1]), "r"(a[2]), "r"(a[3]), "r"(b[0]), "r"(b[1]));
}

#define CP_ASYNC16(dst, src) \
    asm volatile("cp.async.cg.shared.global [%0], [%1], 16;" :: "r"(dst), "l"(src) : "memory")
#define CP_COMMIT() asm volatile("cp.async.commit_group;" ::: "memory")
#define CP_WAIT0()  asm volatile("cp.async.wait_group 0;" ::: "memory")

__device__ __forceinline__ uint32_t h2pack(float a, float b) {
    __half2 h = __floats2half2_rn(a, b);
    return *reinterpret_cast<uint32_t*>(&h);
}

// ---------------- weight prepack (+ accumulator zeroing in low blocks) ----------------
__global__ void wprep_kernel(const float* __restrict__ w) {
    int idx = blockIdx.x * 256 + threadIdx.x;
    // fold zero_kernel in: first 21156/?.. indices cover sums+cnt
    if (idx < BATCH * NCLS * CH) { g_sum_d[idx] = 0.f; g_sum_f[idx] = 0.f; }
    if (idx < BATCH * NCLS) g_cnt[idx] = 0.f;
    if (idx >= 36 * CH * 64) return;
    int kk = idx & 63;
    int oc = (idx >> 6) & 127;
    int t  = idx >> 13;          // 0..35 : tap f = t>>2, ci-block = t&3
    int f  = t >> 2;
    int ci = (t & 3) * 64 + kk;
    float wv = w[(size_t)(oc * CIN + ci) * 9 + f];
    uint32_t off = ((uint32_t)oc << 7) + (((uint32_t)kk * 2) ^ (((uint32_t)(oc & 7)) << 4));
    *(__half*)((char*)g_bt4 + (size_t)t * 16384 + off) = __float2half(wv);
}

// ---------------- prep + RA(d) fused ----------------
// grid (HW/1024, BATCH, 4); block 256. Each block: 1024 pixels x 32 channels.
__global__ void prep_ra_kernel(const float* __restrict__ r, const float* __restrict__ dd,
                               const int* __restrict__ label) {
    __shared__ float bins[NCLS * 33];
    __shared__ float cnts[NCLS];
    __shared__ int   slab[1024];

    const int b   = blockIdx.y;
    const int c0  = blockIdx.z * 32;
    const int p0  = blockIdx.x * 1024;
    const int tid = threadIdx.x;

    for (int i = tid; i < NCLS * 33; i += 256) bins[i] = 0.f;
    if (tid < NCLS) cnts[tid] = 0.f;
    for (int i = tid; i < 1024; i += 256) {
        int p = p0 + i;
        int y = p / WW;
        int x = p - y * WW;
        slab[i] = label[(size_t)b * 896 * 896 + (size_t)(4 * y) * 896 + 4 * x];
    }
    __syncthreads();

    if (blockIdx.z == 0) {
        for (int i = tid; i < 1024; i += 256) atomicAdd(&cnts[slab[i]], 1.f);
    }

    const int i4 = tid * 4;
    const int l0 = slab[i4], l1 = slab[i4 + 1], l2 = slab[i4 + 2], l3 = slab[i4 + 3];
    uint32_t* xb = g_xh2 + (size_t)b * 128 * HW;

    for (int c = 0; c < 32; c += 2) {
        size_t off0 = ((size_t)(b * CH + c0 + c)) * HW + p0 + i4;
        float4 rv0 = *reinterpret_cast<const float4*>(r + off0);
        float4 dv0 = *reinterpret_cast<const float4*>(dd + off0);
        float4 rv1 = *reinterpret_cast<const float4*>(r + off0 + HW);
        float4 dv1 = *reinterpret_cast<const float4*>(dd + off0 + HW);

        atomicAdd(&bins[l0 * 33 + c], dv0.x);
        atomicAdd(&bins[l1 * 33 + c], dv0.y);
        atomicAdd(&bins[l2 * 33 + c], dv0.z);
        atomicAdd(&bins[l3 * 33 + c], dv0.w);
        atomicAdd(&bins[l0 * 33 + c + 1], dv1.x);
        atomicAdd(&bins[l1 * 33 + c + 1], dv1.y);
        atomicAdd(&bins[l2 * 33 + c + 1], dv1.z);
        atomicAdd(&bins[l3 * 33 + c + 1], dv1.w);

        uint4 ap, mp;
        ap.x = h2pack(rv0.x + dv0.x, rv1.x + dv1.x);
        ap.y = h2pack(rv0.y + dv0.y, rv1.y + dv1.y);
        ap.z = h2pack(rv0.z + dv0.z, rv1.z + dv1.z);
        ap.w = h2pack(rv0.w + dv0.w, rv1.w + dv1.w);
        mp.x = h2pack(rv0.x * sigmoid_fast(dv0.x), rv1.x * sigmoid_fast(dv1.x));
        mp.y = h2pack(rv0.y * sigmoid_fast(dv0.y), rv1.y * sigmoid_fast(dv1.y));
        mp.z = h2pack(rv0.z * sigmoid_fast(dv0.z), rv1.z * sigmoid_fast(dv1.z));
        mp.w = h2pack(rv0.w * sigmoid_fast(dv0.w), rv1.w * sigmoid_fast(dv1.w));

        const int cp = (c0 + c) >> 1;      // pair index within add plane
        *reinterpret_cast<uint4*>(xb + ((size_t)cp) * HW + p0 + i4)        = ap;
        *reinterpret_cast<uint4*>(xb + ((size_t)(64 + cp)) * HW + p0 + i4) = mp;
    }
    __syncthreads();

    for (int i = tid; i < NCLS * 32; i += 256) {
        int k = i >> 5;
        int c = i & 31;
        atomicAdd(&g_sum_d[((size_t)b * NCLS + k) * CH + c0 + c], bins[k * 33 + c]);
    }
    if (blockIdx.z == 0 && tid < NCLS) atomicAdd(&g_cnt[b * NCLS + tid], cnts[tid]);
}

// ---------------- RA finalize ----------------
__global__ void ra_finalize_kernel(const float* __restrict__ w1_d, const float* __restrict__ w2_d,
                                   const float* __restrict__ w1_f, const float* __restrict__ w2_f) {
    const int which = blockIdx.x & 1;
    const int b     = blockIdx.x >> 1;
    const float* sums = which ? g_sum_f : g_sum_d;
    const float* w1   = which ? w1_f : w1_d;
    const float* w2   = which ? w2_f : w2_d;

    __shared__ float att[CH];
    __shared__ float hid[8];
    const int c = threadIdx.x;  // 128 threads

    float s1 = 0.f, s2 = 0.f;
    for (int k = 0; k < NCLS; k++) {
        float cnt = g_cnt[b * NCLS + k];
        float m = sums[((size_t)b * NCLS + k) * CH + c] / fmaxf(cnt, 1.f);
        s1 += m;
        s2 += m * m;
    }
    float nrm = fmaxf(sqrtf(s2), 1e-12f);
    att[c] = s1 / nrm;
    __syncthreads();

    if (c < 8) {
        float h = 0.f;
        for (int j = 0; j < CH; j++) h += att[j] * w1[c * CH + j];
        hid[c] = fmaxf(h, 0.f);
    }
    __syncthreads();

    float o = 0.f;
    #pragma unroll
    for (int j = 0; j < 8; j++) o += hid[j] * w2[c * 8 + j];
    g_scale[(which * BATCH + b) * CH + c] = 1.f / (1.f + expf(-o));
}

// ---------------- conv: mma.sync fp16 single-term, 2-stage pipeline, fused RA(fuse) ----------------
// CTA: 128 pixels x 128 oc.  36 chunks = 9 taps x 4 ci-blocks of 64 channels.
// Stage (32KB): A tile 16KB (128 px rows x 64 fp16 ch, SW128) + B tile 16KB (128 oc x 64 ch).
// 2 stages = 64KB.  Prefetch chunk c+1 (A LDGs in regs, B cp.async) overlaps MMA of chunk c.
// (R13 mainloop structure: prefetched-A STS after the full MMA loop.)
#define CONV_SMEM 65536

__device__ __forceinline__ void conv_store_a(char* aRow, const uint32_t* xs,
                                             int half, uint32_t swx) {
    #pragma unroll
    for (int q = 0; q < 4; q++) {
        uint4 v;
        v.x = xs[4 * q];  v.y = xs[4 * q + 1];  v.z = xs[4 * q + 2];  v.w = xs[4 * q + 3];
        uint32_t co = ((uint32_t)(half * 64 + 16 * q)) ^ swx;
        *(uint4*)(aRow + co) = v;
    }
}

__global__ __launch_bounds__(256, 2) void conv_mma_kernel(const int* __restrict__ label) {
    extern __shared__ __align__(1024) char smem[];
    const uint32_t sb = smem_u32(smem);
    const int tid  = threadIdx.x;
    const int wid  = tid >> 5;
    const int lane = tid & 31;
    const int b    = blockIdx.y;
    const int p0   = blockIdx.x * 128;

    const int wm = wid & 1;        // M warp (0..1) -> 64 pixels
    const int wn = wid >> 1;       // N warp (0..3) -> 32 oc
    const int rln  = lane & 7;
    const int quad = lane >> 3;

    const int a_row_off = rln + ((quad & 1) << 3);
    const uint32_t a_kb = (uint32_t)(quad >> 1) << 4;
    const int b_oc_off  = rln + ((quad >> 1) << 3);
    const uint32_t b_kb = (uint32_t)(quad & 1) << 4;
    const uint32_t lxor = (uint32_t)rln << 4;

    const uint32_t aBase = sb + (uint32_t)(wm * 64 + a_row_off) * 128;
    const uint32_t bBase = sb + 16384 + (uint32_t)(wn * 32 + b_oc_off) * 128;

    // loader mapping: 2 threads per pixel row, each 16 channel-pairs (32 ch)
    const int row  = tid >> 1;
    const int half = tid & 1;
    const int p    = p0 + row;
    const int py   = p / WW;
    const int px   = p - py * WW;
    const uint32_t swx = (uint32_t)(row & 7) << 4;

    float acc[4][4][4];
    #pragma unroll
    for (int i = 0; i < 4; i++)
        #pragma unroll
        for (int j = 0; j < 4; j++)
            #pragma unroll
            for (int k = 0; k < 4; k++) acc[i][j][k] = 0.f;

    uint32_t xs[16];

    // ---- prologue: chunk 0 -> stage 0 ----
    {
        const int iy = py - 1, ix = px - 1;
        const bool valid = ((unsigned)iy < (unsigned)HH) && ((unsigned)ix < (unsigned)WW);
        const uint32_t* sp = g_xh2 + ((size_t)(b * 128 + half * 16)) * HW + (iy * WW + ix);
        #pragma unroll
        for (int e = 0; e < 16; e++) xs[e] = valid ? sp[(size_t)e * HW] : 0u;
        const char* bsrc = (const char*)g_bt4 + tid * 16;
        uint32_t bd = sb + 16384 + tid * 16;
        #pragma unroll
        for (int i = 0; i < 4; i++) CP_ASYNC16(bd + i * 4096, bsrc + i * 4096);
        CP_COMMIT();
        conv_store_a(smem + row * 128, xs, half, swx);
    }
    CP_WAIT0();
    __syncthreads();

    for (int c = 0; c < 36; c++) {
        const int s = c & 1;

        // prefetch chunk c+1: A LDGs into regs (latency hides under MMA), B via cp.async
        if (c < 35) {
            const int cn = c + 1;
            const int f  = cn >> 2;
            const int cc = cn & 3;
            const int fy = f / 3;
            const int iy = py + fy - 1;
            const int ix = px + (f - fy * 3) - 1;
            const bool valid = ((unsigned)iy < (unsigned)HH) && ((unsigned)ix < (unsigned)WW);
            const uint32_t* sp = g_xh2 + ((size_t)(b * 128 + cc * 32 + half * 16)) * HW
                                       + (iy * WW + ix);
            #pragma unroll
            for (int e = 0; e < 16; e++) xs[e] = valid ? sp[(size_t)e * HW] : 0u;

            const char* bsrc = (const char*)g_bt4 + (size_t)cn * 16384 + tid * 16;
            uint32_t bd = sb + (uint32_t)(s ^ 1) * 32768 + 16384 + tid * 16;
            #pragma unroll
            for (int i = 0; i < 4; i++) CP_ASYNC16(bd + i * 4096, bsrc + i * 4096);
            CP_COMMIT();
        }

        // ---- MMA on stage s: K = 64 ch = 4 k16 steps, single fp16 term ----
        const uint32_t aB = aBase + (uint32_t)s * 32768;
        const uint32_t bB = bBase + (uint32_t)s * 32768;
        #pragma unroll
        for (int ks = 0; ks < 4; ks++) {
            const uint32_t aco = ((uint32_t)(ks * 32) + a_kb) ^ lxor;
            const uint32_t bco = ((uint32_t)(ks * 32) + b_kb) ^ lxor;

            uint32_t Bf[2][4];
            ldsm4(Bf[0], bB + bco);
            ldsm4(Bf[1], bB + 2048 + bco);
            #pragma unroll
            for (int mf = 0; mf < 4; mf++) {
                uint32_t Af[4];
                ldsm4(Af, aB + mf * 2048 + aco);
                mma16816(acc[mf][0], Af, Bf[0]);
                mma16816(acc[mf][1], Af, Bf[0] + 2);
                mma16816(acc[mf][2], Af, Bf[1]);
                mma16816(acc[mf][3], Af, Bf[1] + 2);
            }
        }

        // store prefetched A into stage s^1 (post-MMA, R13 placement)
        if (c < 35) {
            conv_store_a(smem + (size_t)(s ^ 1) * 32768 + row * 128, xs, half, swx);
        }
        CP_WAIT0();
        __syncthreads();
    }

    // ---- fused epilogue: write g_fuse_h (fp16) + RA(fuse) bins ----
    float* bins = (float*)smem;                    // 41*129 floats = 21156 B
    int*   slb  = (int*)(smem + 21248);            // 128 labels
    for (int i = tid; i < NCLS * 129; i += 256) bins[i] = 0.f;
    if (tid < 128) {
        int pp = p0 + tid;
        int yy = pp / WW;
        int xx = pp - yy * WW;
        slb[tid] = label[(size_t)b * 896 * 896 + (size_t)(4 * yy) * 896 + 4 * xx];
    }
    __syncthreads();

    __half* fb = g_fuse_h + (size_t)b * CH * HW;
    const int prl = wm * 64 + (lane >> 2);
    const int oc0 = wn * 32 + (lane & 3) * 2;
    #pragma unroll
    for (int mf = 0; mf < 4; mf++) {
        const int px0 = prl + mf * 16;
        const int la  = slb[px0];
        const int lb2 = slb[px0 + 8];
        #pragma unroll
        for (int nf = 0; nf < 4; nf++) {
            const int oc = oc0 + nf * 8;
            float v0 = acc[mf][nf][0], v1 = acc[mf][nf][1];
            float v2 = acc[mf][nf][2], v3 = acc[mf][nf][3];
            fb[(size_t)oc * HW + p0 + px0]           = __float2half(v0);
            fb[(size_t)(oc + 1) * HW + p0 + px0]     = __float2half(v1);
            fb[(size_t)oc * HW + p0 + px0 + 8]       = __float2half(v2);
            fb[(size_t)(oc + 1) * HW + p0 + px0 + 8] = __float2half(v3);
            atomicAdd(&bins[la * 129 + oc], v0);
            atomicAdd(&bins[la * 129 + oc + 1], v1);
            atomicAdd(&bins[lb2 * 129 + oc], v2);
            atomicAdd(&bins[lb2 * 129 + oc + 1], v3);
        }
    }
    __syncthreads();
    for (int i = tid; i < NCLS * CH; i += 256) {
        int k = i >> 7;
        int c = i & 127;
        atomicAdd(&g_sum_f[((size_t)b * NCLS + k) * CH + c], bins[k * 129 + c]);
    }
}

// ---------------- final: out = fuse*scale_f + d*scale_d (fuse fp16, 8 px/thread) ----------------
__global__ void final_kernel(const float* __restrict__ dd, float* __restrict__ out) {
    int idx = blockIdx.x * 256 + threadIdx.x;
    const int n8 = BATCH * CH * HW / 8;
    if (idx >= n8) return;
    int i = idx * 8;
    int bc = i / HW;
    int b = bc >> 7;
    int c = bc & (CH - 1);
    float sd = g_scale[b * CH + c];
    float sf = g_scale[(BATCH + b) * CH + c];

    uint4 fv = *reinterpret_cast<const uint4*>(g_fuse_h + i);   // 8 halfs
    float4 d0 = *reinterpret_cast<const float4*>(dd + i);
    float4 d1 = *reinterpret_cast<const float4*>(dd + i + 4);

    float2 f0 = __half22float2(*reinterpret_cast<__half2*>(&fv.x));
    float2 f1 = __half22float2(*reinterpret_cast<__half2*>(&fv.y));
    float2 f2 = __half22float2(*reinterpret_cast<__half2*>(&fv.z));
    float2 f3 = __half22float2(*reinterpret_cast<__half2*>(&fv.w));

    float4 o0, o1;
    o0.x = f0.x * sf + d0.x * sd;
    o0.y = f0.y * sf + d0.y * sd;
    o0.z = f1.x * sf + d0.z * sd;
    o0.w = f1.y * sf + d0.w * sd;
    o1.x = f2.x * sf + d1.x * sd;
    o1.y = f2.y * sf + d1.y * sd;
    o1.z = f3.x * sf + d1.z * sd;
    o1.w = f3.y * sf + d1.w * sd;
    *reinterpret_cast<float4*>(out + i)     = o0;
    *reinterpret_cast<float4*>(out + i + 4) = o1;
}

// ---------------- launcher ----------------
extern "C" void kernel_launch(void* const* d_in, const int* in_sizes, int n_in,
                              void* d_out, int out_size) {
    const float* r      = (const float*)d_in[0];
    const float* d      = (const float*)d_in[1];
    const int*   label  = (const int*)  d_in[2];
    const float* w_fuse = (const float*)d_in[3];
    const float* w1_d   = (const float*)d_in[4];
    const float* w2_d   = (const float*)d_in[5];
    const float* w1_f   = (const float*)d_in[6];
    const float* w2_f   = (const float*)d_in[7];
    float* out = (float*)d_out;

    static int smem_set = 0;
    if (!smem_set) {
        cudaFuncSetAttribute(conv_mma_kernel, cudaFuncAttributeMaxDynamicSharedMemorySize, CONV_SMEM);
        smem_set = 1;
    }

    const int n8 = BATCH * CH * HW / 8;

    wprep_kernel<<<(36 * CH * 64 + 255) / 256, 256>>>(w_fuse);                     // 1 (also zeroes sums)
    prep_ra_kernel<<<dim3(HW / 1024, BATCH, 4), 256>>>(r, d, label);               // 2
    conv_mma_kernel<<<dim3(HW / 128, BATCH), 256, CONV_SMEM>>>(label);             // 3
    ra_finalize_kernel<<<2 * BATCH, CH>>>(w1_d, w2_d, w1_f, w2_f);                 // 4
    final_kernel<<<(n8 + 255) / 256, 256>>>(d, out);                               // 5
}

// round 17
// speedup vs baseline: 1.6794x; 1.0094x over previous
#include <cuda_runtime.h>
#include <cuda_fp16.h>
#include <cstdint>

#define BATCH 4
#define CH    128
#define CIN   256
#define HH    224
#define WW    224
#define HW    50176
#define NCLS  41

// ---------------------------------------------------------------------------
// scratch (static device globals; no allocs)
// ---------------------------------------------------------------------------
// g_xh2: fp16 channel-PAIR packed planes: word = (fp16 x[2cp], fp16 x[2cp+1]) per pixel.
// cp in [0,64) = add-plane pairs, [64,128) = mul-plane pairs.
static __device__ uint32_t g_xh2[(size_t)BATCH * 128 * HW];
static __device__ __half   g_fuse_h[(size_t)BATCH * CH * HW];  // conv output (fp16, channel-major)
static __device__ uint4    g_bt4[36 * 1024];                   // 36 chunks x 16KB SW128 fp16 B images
static __device__ float    g_sum_d[BATCH * NCLS * CH];
static __device__ float    g_sum_f[BATCH * NCLS * CH];
static __device__ float    g_cnt[BATCH * NCLS];
static __device__ float    g_scale[2 * BATCH * CH];

__device__ __forceinline__ float sigmoid_fast(float x) { return 1.f / (1.f + __expf(-x)); }

__device__ __forceinline__ uint32_t smem_u32(const void* p) {
    uint32_t a;
    asm("{ .reg .u64 t; cvta.to.shared.u64 t, %1; cvt.u32.u64 %0, t; }" : "=r"(a) : "l"(p));
    return a;
}

__device__ __forceinline__ void ldsm4(uint32_t* r, uint32_t addr) {
    asm volatile("ldmatrix.sync.aligned.m8n8.x4.shared.b16 {%0,%1,%2,%3}, [%4];"
                 : "=r"(r[0]), "=r"(r[1]), "=r"(r[2]), "=r"(r[3]) : "r"(addr));
}

__device__ __forceinline__ void mma16816(float* c, const uint32_t* a, const uint32_t* b) {
    asm volatile(
        "mma.sync.aligned.m16n8k16.row.col.f32.f16.f16.f32 "
        "{%0,%1,%2,%3}, {%4,%5,%6,%7}, {%8,%9}, {%0,%1,%2,%3};"
        : "+f"(c[0]), "+f"(c[1]), "+f"(c[2]), "+f"(c[3])
        : "r"(a[0]), "r"(a[1]), "r"(a[2]), "r"(a[3]), "r"(b[0]), "r"(b[1]));
}

#define CP_ASYNC16(dst, src) \
    asm volatile("cp.async.cg.shared.global [%0], [%1], 16;" :: "r"(dst), "l"(src) : "memory")
#define CP_COMMIT() asm volatile("cp.async.commit_group;" ::: "memory")
#define CP_WAIT0()  asm volatile("cp.async.wait_group 0;" ::: "memory")

__device__ __forceinline__ uint32_t h2pack(float a, float b) {
    __half2 h = __floats2half2_rn(a, b);
    return *reinterpret_cast<uint32_t*>(&h);
}

// ---------------- weight prepack (+ accumulator zeroing in low blocks) ----------------
__global__ void wprep_kernel(const float* __restrict__ w) {
    int idx = blockIdx.x * 256 + threadIdx.x;
    if (idx < BATCH * NCLS * CH) { g_sum_d[idx] = 0.f; g_sum_f[idx] = 0.f; }
    if (idx < BATCH * NCLS) g_cnt[idx] = 0.f;
    if (idx >= 36 * CH * 64) return;
    int kk = idx & 63;
    int oc = (idx >> 6) & 127;
    int t  = idx >> 13;          // 0..35 : tap f = t>>2, ci-block = t&3
    int f  = t >> 2;
    int ci = (t & 3) * 64 + kk;
    float wv = w[(size_t)(oc * CIN + ci) * 9 + f];
    uint32_t off = ((uint32_t)oc << 7) + (((uint32_t)kk * 2) ^ (((uint32_t)(oc & 7)) << 4));
    *(__half*)((char*)g_bt4 + (size_t)t * 16384 + off) = __float2half(wv);
}

// ---------------- prep + RA(d) fused ----------------
// grid (HW/1024, BATCH, 4); block 256. Each block: 1024 pixels x 32 channels.
__global__ void prep_ra_kernel(const float* __restrict__ r, const float* __restrict__ dd,
                               const int* __restrict__ label) {
    __shared__ float bins[NCLS * 33];
    __shared__ float cnts[NCLS];
    __shared__ int   slab[1024];

    const int b   = blockIdx.y;
    const int c0  = blockIdx.z * 32;
    const int p0  = blockIdx.x * 1024;
    const int tid = threadIdx.x;

    for (int i = tid; i < NCLS * 33; i += 256) bins[i] = 0.f;
    if (tid < NCLS) cnts[tid] = 0.f;
    for (int i = tid; i < 1024; i += 256) {
        int p = p0 + i;
        int y = p / WW;
        int x = p - y * WW;
        slab[i] = label[(size_t)b * 896 * 896 + (size_t)(4 * y) * 896 + 4 * x];
    }
    __syncthreads();

    if (blockIdx.z == 0) {
        for (int i = tid; i < 1024; i += 256) atomicAdd(&cnts[slab[i]], 1.f);
    }

    const int i4 = tid * 4;
    const int l0 = slab[i4], l1 = slab[i4 + 1], l2 = slab[i4 + 2], l3 = slab[i4 + 3];
    uint32_t* xb = g_xh2 + (size_t)b * 128 * HW;

    for (int c = 0; c < 32; c += 2) {
        size_t off0 = ((size_t)(b * CH + c0 + c)) * HW + p0 + i4;
        float4 rv0 = *reinterpret_cast<const float4*>(r + off0);
        float4 dv0 = *reinterpret_cast<const float4*>(dd + off0);
        float4 rv1 = *reinterpret_cast<const float4*>(r + off0 + HW);
        float4 dv1 = *reinterpret_cast<const float4*>(dd + off0 + HW);

        atomicAdd(&bins[l0 * 33 + c], dv0.x);
        atomicAdd(&bins[l1 * 33 + c], dv0.y);
        atomicAdd(&bins[l2 * 33 + c], dv0.z);
        atomicAdd(&bins[l3 * 33 + c], dv0.w);
        atomicAdd(&bins[l0 * 33 + c + 1], dv1.x);
        atomicAdd(&bins[l1 * 33 + c + 1], dv1.y);
        atomicAdd(&bins[l2 * 33 + c + 1], dv1.z);
        atomicAdd(&bins[l3 * 33 + c + 1], dv1.w);

        uint4 ap, mp;
        ap.x = h2pack(rv0.x + dv0.x, rv1.x + dv1.x);
        ap.y = h2pack(rv0.y + dv0.y, rv1.y + dv1.y);
        ap.z = h2pack(rv0.z + dv0.z, rv1.z + dv1.z);
        ap.w = h2pack(rv0.w + dv0.w, rv1.w + dv1.w);
        mp.x = h2pack(rv0.x * sigmoid_fast(dv0.x), rv1.x * sigmoid_fast(dv1.x));
        mp.y = h2pack(rv0.y * sigmoid_fast(dv0.y), rv1.y * sigmoid_fast(dv1.y));
        mp.z = h2pack(rv0.z * sigmoid_fast(dv0.z), rv1.z * sigmoid_fast(dv1.z));
        mp.w = h2pack(rv0.w * sigmoid_fast(dv0.w), rv1.w * sigmoid_fast(dv1.w));

        const int cp = (c0 + c) >> 1;      // pair index within add plane
        *reinterpret_cast<uint4*>(xb + ((size_t)cp) * HW + p0 + i4)        = ap;
        *reinterpret_cast<uint4*>(xb + ((size_t)(64 + cp)) * HW + p0 + i4) = mp;
    }
    __syncthreads();

    for (int i = tid; i < NCLS * 32; i += 256) {
        int k = i >> 5;
        int c = i & 31;
        atomicAdd(&g_sum_d[((size_t)b * NCLS + k) * CH + c0 + c], bins[k * 33 + c]);
    }
    if (blockIdx.z == 0 && tid < NCLS) atomicAdd(&g_cnt[b * NCLS + tid], cnts[tid]);
}

// ---------------- RA finalize (k-loop fully unrolled for MLP) ----------------
__global__ void ra_finalize_kernel(const float* __restrict__ w1_d, const float* __restrict__ w2_d,
                                   const float* __restrict__ w1_f, const float* __restrict__ w2_f) {
    const int which = blockIdx.x & 1;
    const int b     = blockIdx.x >> 1;
    const float* sums = which ? g_sum_f : g_sum_d;
    const float* w1   = which ? w1_f : w1_d;
    const float* w2   = which ? w2_f : w2_d;

    __shared__ float att[CH];
    __shared__ float hid[8];
    const int c = threadIdx.x;  // 128 threads

    float m[NCLS];
    #pragma unroll
    for (int k = 0; k < NCLS; k++)
        m[k] = sums[((size_t)b * NCLS + k) * CH + c] / fmaxf(g_cnt[b * NCLS + k], 1.f);
    float s1 = 0.f, s2 = 0.f;
    #pragma unroll
    for (int k = 0; k < NCLS; k++) { s1 += m[k]; s2 += m[k] * m[k]; }
    float nrm = fmaxf(sqrtf(s2), 1e-12f);
    att[c] = s1 / nrm;
    __syncthreads();

    if (c < 8) {
        float h = 0.f;
        #pragma unroll 8
        for (int j = 0; j < CH; j++) h += att[j] * w1[c * CH + j];
        hid[c] = fmaxf(h, 0.f);
    }
    __syncthreads();

    float o = 0.f;
    #pragma unroll
    for (int j = 0; j < 8; j++) o += hid[j] * w2[c * 8 + j];
    g_scale[(which * BATCH + b) * CH + c] = 1.f / (1.f + expf(-o));
}

// ---------------- conv: fp16 mma.sync, 4-warp 2x2 grid, 64x64 warp tiles ----------------
// CTA: 128 threads, 128 pixels x 128 oc.  36 chunks = 9 taps x 4 ci-blocks of 64 ch.
// Warp tile 64px x 64oc (acc = 128 fp32; 256-reg budget via __launch_bounds__(128,2)).
// LDSM/chunk = A x2 + B x2 = 64KB (vs 96KB at 8 warps) -> crossbar floor down 33%.
// Stage (32KB): A 16KB + B 16KB; 2 stages = 64KB; A LDG prefetch + B cp.async as before.
#define CONV_SMEM 65536

__device__ __forceinline__ void conv_store_a(char* aRow, const uint32_t* xs, uint32_t swx) {
    #pragma unroll
    for (int q = 0; q < 8; q++) {
        uint4 v;
        v.x = xs[4 * q];  v.y = xs[4 * q + 1];  v.z = xs[4 * q + 2];  v.w = xs[4 * q + 3];
        uint32_t co = ((uint32_t)(16 * q)) ^ swx;
        *(uint4*)(aRow + co) = v;
    }
}

__global__ __launch_bounds__(128, 2) void conv_mma_kernel(const int* __restrict__ label) {
    extern __shared__ __align__(1024) char smem[];
    const uint32_t sb = smem_u32(smem);
    const int tid  = threadIdx.x;
    const int wid  = tid >> 5;
    const int lane = tid & 31;
    const int b    = blockIdx.y;
    const int p0   = blockIdx.x * 128;

    const int wm = wid & 1;        // M warp (0..1) -> 64 pixels
    const int wn = wid >> 1;       // N warp (0..1) -> 64 oc
    const int rln  = lane & 7;
    const int quad = lane >> 3;

    const int a_row_off = rln + ((quad & 1) << 3);
    const uint32_t a_kb = (uint32_t)(quad >> 1) << 4;
    const int b_oc_off  = rln + ((quad >> 1) << 3);
    const uint32_t b_kb = (uint32_t)(quad & 1) << 4;
    const uint32_t lxor = (uint32_t)rln << 4;

    const uint32_t aBase = sb + (uint32_t)(wm * 64 + a_row_off) * 128;
    const uint32_t bBase = sb + 16384 + (uint32_t)(wn * 64 + b_oc_off) * 128;

    // loader mapping: ONE thread per pixel row (32 words = full 64-ch chunk)
    const int row = tid;
    const int p   = p0 + row;
    const int py  = p / WW;
    const int px  = p - py * WW;
    const uint32_t swx = (uint32_t)(row & 7) << 4;

    float acc[4][8][4];
    #pragma unroll
    for (int i = 0; i < 4; i++)
        #pragma unroll
        for (int j = 0; j < 8; j++)
            #pragma unroll
            for (int k = 0; k < 4; k++) acc[i][j][k] = 0.f;

    uint32_t xs[32];

    // ---- prologue: chunk 0 -> stage 0 ----
    {
        const int iy = py - 1, ix = px - 1;
        const bool valid = ((unsigned)iy < (unsigned)HH) && ((unsigned)ix < (unsigned)WW);
        const uint32_t* sp = g_xh2 + ((size_t)(b * 128)) * HW + (iy * WW + ix);
        #pragma unroll
        for (int e = 0; e < 32; e++) xs[e] = valid ? sp[(size_t)e * HW] : 0u;
        const char* bsrc = (const char*)g_bt4 + tid * 16;
        uint32_t bd = sb + 16384 + tid * 16;
        #pragma unroll
        for (int i = 0; i < 8; i++) CP_ASYNC16(bd + i * 2048, bsrc + i * 2048);
        CP_COMMIT();
        conv_store_a(smem + row * 128, xs, swx);
    }
    CP_WAIT0();
    __syncthreads();

    for (int c = 0; c < 36; c++) {
        const int s = c & 1;

        // prefetch chunk c+1: A LDGs into regs, B via cp.async
        if (c < 35) {
            const int cn = c + 1;
            const int f  = cn >> 2;
            const int cc = cn & 3;
            const int fy = f / 3;
            const int iy = py + fy - 1;
            const int ix = px + (f - fy * 3) - 1;
            const bool valid = ((unsigned)iy < (unsigned)HH) && ((unsigned)ix < (unsigned)WW);
            const uint32_t* sp = g_xh2 + ((size_t)(b * 128 + cc * 32)) * HW + (iy * WW + ix);
            #pragma unroll
            for (int e = 0; e < 32; e++) xs[e] = valid ? sp[(size_t)e * HW] : 0u;

            const char* bsrc = (const char*)g_bt4 + (size_t)cn * 16384 + tid * 16;
            uint32_t bd = sb + (uint32_t)(s ^ 1) * 32768 + 16384 + tid * 16;
            #pragma unroll
            for (int i = 0; i < 8; i++) CP_ASYNC16(bd + i * 2048, bsrc + i * 2048);
            CP_COMMIT();
        }

        // ---- MMA on stage s: K = 64 ch = 4 k16 steps ----
        const uint32_t aB = aBase + (uint32_t)s * 32768;
        const uint32_t bB = bBase + (uint32_t)s * 32768;
        #pragma unroll
        for (int ks = 0; ks < 4; ks++) {
            const uint32_t aco = ((uint32_t)(ks * 32) + a_kb) ^ lxor;
            const uint32_t bco = ((uint32_t)(ks * 32) + b_kb) ^ lxor;

            uint32_t Bf[4][4];
            #pragma unroll
            for (int ng = 0; ng < 4; ng++) ldsm4(Bf[ng], bB + ng * 2048 + bco);
            #pragma unroll
            for (int mf = 0; mf < 4; mf++) {
                uint32_t Af[4];
                ldsm4(Af, aB + mf * 2048 + aco);
                #pragma unroll
                for (int ng = 0; ng < 4; ng++) {
                    mma16816(acc[mf][2 * ng],     Af, Bf[ng]);
                    mma16816(acc[mf][2 * ng + 1], Af, Bf[ng] + 2);
                }
            }
        }

        // store prefetched A into stage s^1 (post-MMA)
        if (c < 35) {
            conv_store_a(smem + (size_t)(s ^ 1) * 32768 + row * 128, xs, swx);
        }
        CP_WAIT0();
        __syncthreads();
    }

    // ---- fused epilogue: write g_fuse_h (fp16) + RA(fuse) bins ----
    float* bins = (float*)smem;                    // 41*129 floats = 21156 B
    int*   slb  = (int*)(smem + 21248);            // 128 labels
    for (int i = tid; i < NCLS * 129; i += 128) bins[i] = 0.f;
    {
        int pp = p0 + tid;
        int yy = pp / WW;
        int xx = pp - yy * WW;
        slb[tid] = label[(size_t)b * 896 * 896 + (size_t)(4 * yy) * 896 + 4 * xx];
    }
    __syncthreads();

    __half* fb = g_fuse_h + (size_t)b * CH * HW;
    const int prl = wm * 64 + (lane >> 2);
    const int oc0 = wn * 64 + (lane & 3) * 2;
    #pragma unroll
    for (int mf = 0; mf < 4; mf++) {
        const int px0 = prl + mf * 16;
        const int la  = slb[px0];
        const int lb2 = slb[px0 + 8];
        #pragma unroll
        for (int nf = 0; nf < 8; nf++) {
            const int oc = oc0 + nf * 8;
            float v0 = acc[mf][nf][0], v1 = acc[mf][nf][1];
            float v2 = acc[mf][nf][2], v3 = acc[mf][nf][3];
            fb[(size_t)oc * HW + p0 + px0]           = __float2half(v0);
            fb[(size_t)(oc + 1) * HW + p0 + px0]     = __float2half(v1);
            fb[(size_t)oc * HW + p0 + px0 + 8]       = __float2half(v2);
            fb[(size_t)(oc + 1) * HW + p0 + px0 + 8] = __float2half(v3);
            atomicAdd(&bins[la * 129 + oc], v0);
            atomicAdd(&bins[la * 129 + oc + 1], v1);
            atomicAdd(&bins[lb2 * 129 + oc], v2);
            atomicAdd(&bins[lb2 * 129 + oc + 1], v3);
        }
    }
    __syncthreads();
    for (int i = tid; i < NCLS * CH; i += 128) {
        int k = i >> 7;
        int c = i & 127;
        atomicAdd(&g_sum_f[((size_t)b * NCLS + k) * CH + c], bins[k * 129 + c]);
    }
}

// ---------------- final: out = fuse*scale_f + d*scale_d (fuse fp16, 8 px/thread) ----------------
__global__ void final_kernel(const float* __restrict__ dd, float* __restrict__ out) {
    int idx = blockIdx.x * 256 + threadIdx.x;
    const int n8 = BATCH * CH * HW / 8;
    if (idx >= n8) return;
    int i = idx * 8;
    int bc = i / HW;
    int b = bc >> 7;
    int c = bc & (CH - 1);
    float sd = g_scale[b * CH + c];
    float sf = g_scale[(BATCH + b) * CH + c];

    uint4 fv = *reinterpret_cast<const uint4*>(g_fuse_h + i);   // 8 halfs
    float4 d0 = *reinterpret_cast<const float4*>(dd + i);
    float4 d1 = *reinterpret_cast<const float4*>(dd + i + 4);

    float2 f0 = __half22float2(*reinterpret_cast<__half2*>(&fv.x));
    float2 f1 = __half22float2(*reinterpret_cast<__half2*>(&fv.y));
    float2 f2 = __half22float2(*reinterpret_cast<__half2*>(&fv.z));
    float2 f3 = __half22float2(*reinterpret_cast<__half2*>(&fv.w));

    float4 o0, o1;
    o0.x = f0.x * sf + d0.x * sd;
    o0.y = f0.y * sf + d0.y * sd;
    o0.z = f1.x * sf + d0.z * sd;
    o0.w = f1.y * sf + d0.w * sd;
    o1.x = f2.x * sf + d1.x * sd;
    o1.y = f2.y * sf + d1.y * sd;
    o1.z = f3.x * sf + d1.z * sd;
    o1.w = f3.y * sf + d1.w * sd;
    *reinterpret_cast<float4*>(out + i)     = o0;
    *reinterpret_cast<float4*>(out + i + 4) = o1;
}

// ---------------- launcher ----------------
extern "C" void kernel_launch(void* const* d_in, const int* in_sizes, int n_in,
                              void* d_out, int out_size) {
    const float* r      = (const float*)d_in[0];
    const float* d      = (const float*)d_in[1];
    const int*   label  = (const int*)  d_in[2];
    const float* w_fuse = (const float*)d_in[3];
    const float* w1_d   = (const float*)d_in[4];
    const float* w2_d   = (const float*)d_in[5];
    const float* w1_f   = (const float*)d_in[6];
    const float* w2_f   = (const float*)d_in[7];
    float* out = (float*)d_out;

    static int smem_set = 0;
    if (!smem_set) {
        cudaFuncSetAttribute(conv_mma_kernel, cudaFuncAttributeMaxDynamicSharedMemorySize, CONV_SMEM);
        smem_set = 1;
    }

    const int n8 = BATCH * CH * HW / 8;

    wprep_kernel<<<(36 * CH * 64 + 255) / 256, 256>>>(w_fuse);                     // 1 (also zeroes sums)
    prep_ra_kernel<<<dim3(HW / 1024, BATCH, 4), 256>>>(r, d, label);               // 2
    conv_mma_kernel<<<dim3(HW / 128, BATCH), 128, CONV_SMEM>>>(label);             // 3
    ra_finalize_kernel<<<2 * BATCH, CH>>>(w1_d, w2_d, w1_f, w2_f);                 // 4
    final_kernel<<<(n8 + 255) / 256, 256>>>(d, out);                               // 5
}